// round 14
// baseline (speedup 1.0000x reference)
#include <cuda_runtime.h>
#include <cuda_bf16.h>
#include <mma.h>
#include <cstdint>

using namespace nvcuda;

#define NB 64
#define NN 1024
#define ND 128
#define THRESH 0.15f      // 0.5 - MARGIN(0.35)
#define TM 128
#define TN 128
#define LDSE 136          // smem leading dim in bf16 elems (272B rows)
#define ROWB (LDSE * 2)
#define TILE_BYTES (TM * ROWB)        // 34816
#define SMEM_DYN (3 * TILE_BYTES)     // A + 2x B = 104448 (occ 2)
#define GEMM_CTAS (8 * NB)            // 512

// Scratch (device globals; no allocation allowed)
__device__ __nv_bfloat16 g_P[(size_t)NB * NN * ND];
__device__ __nv_bfloat16 g_Q[(size_t)NB * NN * ND];
__device__ int   g_npos[NB];
__device__ int   g_nneg[NB];
__device__ float g_bsum[NB];
__device__ unsigned int g_done;

__device__ __forceinline__ uint32_t smem_u32(const void* p) {
    uint32_t a;
    asm("{ .reg .u64 t; cvta.to.shared.u64 t, %1; cvt.u32.u64 %0, t; }" : "=r"(a) : "l"(p));
    return a;
}
__device__ __forceinline__ void cp16(uint32_t dst, const void* src) {
    asm volatile("cp.async.cg.shared.global [%0], [%1], 16;" :: "r"(dst), "l"(src));
}
#define CP_COMMIT() asm volatile("cp.async.commit_group;" ::: "memory")
#define CP_WAIT(n)  asm volatile("cp.async.wait_group %0;" :: "n"(n) : "memory")

// ---------------------------------------------------------------------------
// Kernel A: fused scan + normalize + scatter. grid = (32, 64), 256 threads.
// Each CTA redundantly scans its batch's 1024 labels (4 KB, L2-resident),
// hidden under the CTA's own float4 embedding loads. Normalize path is the
// R13 winner verbatim: 4 rows/warp, MLP=4, batched shfl, packed stores.
// ---------------------------------------------------------------------------
__global__ void __launch_bounds__(256)
normalize_fused_kernel(const float* __restrict__ emb,
                       const int*   __restrict__ labels)
{
    const int b   = blockIdx.y;
    const int tid = threadIdx.x;
    const int warp = tid >> 5, lane = tid & 31;
    const int r0 = blockIdx.x * 32 + warp * 4;    // 4 consecutive rows per warp

    __shared__ int s_wtot[8];
    __shared__ unsigned short s_dest[NN];

    // ---- issue embedding loads FIRST (DRAM, ~600 cyc) ----
    float4 v[4];
#pragma unroll
    for (int j = 0; j < 4; j++)
        v[j] = reinterpret_cast<const float4*>(emb + ((size_t)b * NN + r0 + j) * ND)[lane];

    // ---- label scan executes under the loads (L2-resident, shfl/ALU) ----
    int4 l4 = reinterpret_cast<const int4*>(labels + b * NN)[tid];
    int p0 = (l4.x == 1), p1 = (l4.y == 1), p2 = (l4.z == 1), p3 = (l4.w == 1);
    int tsum = p0 + p1 + p2 + p3;

    int incl = tsum;
#pragma unroll
    for (int o = 1; o < 32; o <<= 1) {
        int u = __shfl_up_sync(0xFFFFFFFFu, incl, o);
        if (lane >= o) incl += u;
    }
    if (lane == 31) s_wtot[warp] = incl;
    __syncthreads();
    if (tid < 8) {
        int w = s_wtot[tid];
#pragma unroll
        for (int o = 1; o < 8; o <<= 1) {
            int u = __shfl_up_sync(0x000000FFu, w, o);
            if (lane >= o) w += u;
        }
        s_wtot[tid] = w;
    }
    __syncthreads();

    int run = (warp > 0 ? s_wtot[warp - 1] : 0) + incl - tsum;
    const int base4 = tid * 4;
    int pp[4] = {p0, p1, p2, p3};
#pragma unroll
    for (int j = 0; j < 4; j++) {
        int idx = base4 + j;
        int rank = pp[j] ? run : (idx - run);
        s_dest[idx] = (unsigned short)(rank | (pp[j] << 15));
        run += pp[j];
    }

    const int npos = s_wtot[7];
    const int nneg = NN - npos;

    // CTA x==0 per batch: publish counts, zero accumulators, pad tile tails
    if (blockIdx.x == 0) {
        if (tid == 0) {
            g_npos[b] = npos; g_nneg[b] = nneg; g_bsum[b] = 0.0f;
            if (b == 0) g_done = 0u;
        }
        const uint4 z4 = make_uint4(0u, 0u, 0u, 0u);
        int pad_pos = min(NN, ((npos + TM - 1) / TM) * TM);
        int pad_neg = min(NN, ((nneg + TN - 1) / TN) * TN);
        int nzp = (pad_pos - npos) * 16;      // 16 uint4 per 256B row
        for (int i = tid; i < nzp; i += 256) {
            int r = npos + (i >> 4), c = i & 15;
            reinterpret_cast<uint4*>(g_P + ((size_t)b * NN + r) * ND)[c] = z4;
        }
        int nzn = (pad_neg - nneg) * 16;
        for (int i = tid; i < nzn; i += 256) {
            int r = nneg + (i >> 4), c = i & 15;
            reinterpret_cast<uint4*>(g_Q + ((size_t)b * NN + r) * ND)[c] = z4;
        }
    }
    __syncthreads();

    // ---- normalize + scatter (R13 winner path) ----
    float ss[4];
#pragma unroll
    for (int j = 0; j < 4; j++)
        ss[j] = v[j].x * v[j].x + v[j].y * v[j].y + v[j].z * v[j].z + v[j].w * v[j].w;
#pragma unroll
    for (int o = 16; o > 0; o >>= 1) {
#pragma unroll
        for (int j = 0; j < 4; j++) ss[j] += __shfl_xor_sync(0xFFFFFFFFu, ss[j], o);
    }

#pragma unroll
    for (int j = 0; j < 4; j++) {
        float inv = 1.0f / fmaxf(sqrtf(ss[j]), 1e-12f);
        unsigned short d = s_dest[r0 + j];
        int rank  = d & 0x7FFF;
        int ispos = d >> 15;
        __nv_bfloat16* dst = (ispos ? g_P : g_Q) + ((size_t)b * NN + rank) * ND;
        __nv_bfloat162 h0 = __floats2bfloat162_rn(v[j].x * inv, v[j].y * inv);
        __nv_bfloat162 h1 = __floats2bfloat162_rn(v[j].z * inv, v[j].w * inv);
        uint2 pk = make_uint2(*reinterpret_cast<uint32_t*>(&h0),
                              *reinterpret_cast<uint32_t*>(&h1));
        reinterpret_cast<uint2*>(dst)[lane] = pk;
    }
}

// ---------------------------------------------------------------------------
// Kernel B: A-resident streaming GEMM (R13 winner, verbatim).
// CTA = (ti, b); A loaded once, B tiles double-buffered. grid (8,64), occ 2.
// ---------------------------------------------------------------------------
__global__ void __launch_bounds__(256, 2)
hinge_gemm_kernel(float* __restrict__ out)
{
    extern __shared__ __align__(16) char smem[];
    const uint32_t smem_base = smem_u32(smem);
    const int tid  = threadIdx.x;
    const int warp = tid >> 5;
    const int lane = tid & 31;

    const int ti = blockIdx.x;
    const int b  = blockIdx.y;
    const int npos = g_npos[b];
    const int nneg = g_nneg[b];
    const int njt  = (nneg + TN - 1) / TN;
    const bool active = (ti * TM < npos) && (njt > 0);

    if (active) {
        const char* P  = (const char*)(g_P + ((size_t)b * NN + ti * TM) * ND);
        const char* Qb = (const char*)(g_Q + (size_t)b * NN * ND);
        const uint32_t sAa  = smem_base;
        const uint32_t sB0a = smem_base + TILE_BYTES;

        for (int t = tid; t < TM * 16; t += 256) {
            int r = t >> 4, c = t & 15;
            cp16(sAa + r * ROWB + c * 16, P + (size_t)r * ND * 2 + c * 16);
            cp16(sB0a + r * ROWB + c * 16, Qb + (size_t)r * ND * 2 + c * 16);
        }
        CP_COMMIT();

        const __nv_bfloat16* sA = (const __nv_bfloat16*)(smem);
        const int wrow = warp >> 1;
        const int wcol = warp & 1;

        float s0 = 0.0f, s1 = 0.0f, s2 = 0.0f, s3 = 0.0f;

        for (int tj = 0; tj < njt; tj++) {
            const int cbuf = tj & 1;
            if (tj + 1 < njt) {
                const char* Qn = Qb + (size_t)(tj + 1) * TN * ND * 2;
                uint32_t sBn = smem_base + TILE_BYTES * (1 + ((tj + 1) & 1));
                for (int t = tid; t < TN * 16; t += 256) {
                    int r = t >> 4, c = t & 15;
                    cp16(sBn + r * ROWB + c * 16, Qn + (size_t)r * ND * 2 + c * 16);
                }
                CP_COMMIT();
                CP_WAIT(1);
            } else {
                CP_WAIT(0);
            }
            __syncthreads();

            const __nv_bfloat16* sB =
                (const __nv_bfloat16*)(smem + TILE_BYTES * (1 + cbuf));

            wmma::fragment<wmma::accumulator, 16, 16, 16, float> acc[2][4];
#pragma unroll
            for (int i = 0; i < 2; i++)
#pragma unroll
                for (int j = 0; j < 4; j++) wmma::fill_fragment(acc[i][j], 0.0f);

#pragma unroll
            for (int k = 0; k < ND; k += 16) {
                wmma::fragment<wmma::matrix_a, 16, 16, 16, __nv_bfloat16, wmma::row_major> a[2];
                wmma::fragment<wmma::matrix_b, 16, 16, 16, __nv_bfloat16, wmma::col_major> bb[4];
#pragma unroll
                for (int i = 0; i < 2; i++)
                    wmma::load_matrix_sync(a[i], sA + (wrow * 32 + i * 16) * LDSE + k, LDSE);
#pragma unroll
                for (int j = 0; j < 4; j++)
                    wmma::load_matrix_sync(bb[j], sB + (wcol * 64 + j * 16) * LDSE + k, LDSE);
#pragma unroll
                for (int i = 0; i < 2; i++)
#pragma unroll
                    for (int j = 0; j < 4; j++)
                        wmma::mma_sync(acc[i][j], a[i], bb[j], acc[i][j]);
            }

            // epilogue: 4 independent partial sums
#pragma unroll
            for (int i = 0; i < 2; i++)
#pragma unroll
                for (int j = 0; j < 4; j++) {
#pragma unroll
                    for (int e = 0; e < 8; e += 4) {
                        s0 += fmaxf(acc[i][j].x[e + 0] - THRESH, 0.0f);
                        s1 += fmaxf(acc[i][j].x[e + 1] - THRESH, 0.0f);
                        s2 += fmaxf(acc[i][j].x[e + 2] - THRESH, 0.0f);
                        s3 += fmaxf(acc[i][j].x[e + 3] - THRESH, 0.0f);
                    }
                }

            __syncthreads();
        }

        float s = (s0 + s1) + (s2 + s3);
#pragma unroll
        for (int o = 16; o > 0; o >>= 1) s += __shfl_xor_sync(0xFFFFFFFFu, s, o);
        __shared__ float s_w[8];
        if (lane == 0) s_w[warp] = s;
        __syncthreads();
        if (tid == 0) {
            float ts = 0.0f;
#pragma unroll
            for (int i = 0; i < 8; i++) ts += s_w[i];
            atomicAdd(&g_bsum[b], ts);
        }
    }

    // completion ticket; last CTA computes the final scalar
    __shared__ unsigned int s_rank;
    if (tid == 0) {
        __threadfence();
        s_rank = atomicAdd(&g_done, 1u);
    }
    __syncthreads();
    if (s_rank == GEMM_CTAS - 1 && tid == 0) {
        __threadfence();
        float L = 0.0f, C = 0.0f;
        for (int i = 0; i < NB; i++) {
            int np = g_npos[i], nn = g_nneg[i];
            if (np > 0 && nn > 0) {
                L += g_bsum[i] / (float)nn;
                C += (float)np;
            }
        }
        out[0] = L / fmaxf(C, 1.0f);
    }
}

// ---------------------------------------------------------------------------
extern "C" void kernel_launch(void* const* d_in, const int* in_sizes, int n_in,
                              void* d_out, int out_size)
{
    const float* emb    = (const float*)d_in[0];
    const int*   labels = (const int*)d_in[1];
    float*       out    = (float*)d_out;

    cudaFuncSetAttribute(hinge_gemm_kernel,
                         cudaFuncAttributeMaxDynamicSharedMemorySize, SMEM_DYN);

    dim3 gridA(NN / 32, NB);   // (32, 64)
    normalize_fused_kernel<<<gridA, 256>>>(emb, labels);

    dim3 gridB(8, NB);         // (ti, b) = 512 CTAs
    hinge_gemm_kernel<<<gridB, 256, SMEM_DYN>>>(out);
}

// round 16
// speedup vs baseline: 1.0775x; 1.0775x over previous
#include <cuda_runtime.h>
#include <cuda_bf16.h>
#include <mma.h>
#include <cstdint>

using namespace nvcuda;

#define NB 64
#define NN 1024
#define NNP 1025          // +1 always-zero row per batch (gather pad target)
#define ND 128
#define THRESH 0.15f      // 0.5 - MARGIN(0.35)
#define TM 128
#define TN 128
#define LDSE 136          // smem leading dim in bf16 elems (272B rows)
#define ROWB (LDSE * 2)
#define TILE_BYTES (TM * ROWB)        // 34816
#define SMEM_DYN (3 * TILE_BYTES)     // A + 2x B = 104448 (+static idx; occ 2)
#define GEMM_CTAS (8 * NB)            // 512

// Scratch (device globals; no allocation allowed).
// g_E row NN of each batch is NEVER written -> stays zero (BSS) across replays.
__device__ __nv_bfloat16 g_E[(size_t)NB * NNP * ND];
__device__ int   g_pidx[NB * NN];
__device__ int   g_nidx[NB * NN];
__device__ int   g_npos[NB];
__device__ int   g_nneg[NB];
__device__ float g_bsum[NB];
__device__ unsigned int g_done;

__device__ __forceinline__ uint32_t smem_u32(const void* p) {
    uint32_t a;
    asm("{ .reg .u64 t; cvta.to.shared.u64 t, %1; cvt.u32.u64 %0, t; }" : "=r"(a) : "l"(p));
    return a;
}
__device__ __forceinline__ void cp16(uint32_t dst, const void* src) {
    asm volatile("cp.async.cg.shared.global [%0], [%1], 16;" :: "r"(dst), "l"(src));
}
#define CP_COMMIT() asm volatile("cp.async.commit_group;" ::: "memory")
#define CP_WAIT(n)  asm volatile("cp.async.wait_group %0;" :: "n"(n) : "memory")

// ---------------------------------------------------------------------------
// Kernel A: grid (33, 64), 256 threads.
//   x < 32 : normalize rows x*32..x*32+31 in NATURAL order (no scan needed)
//   x == 32: scan CTA -> index lists g_pidx/g_nidx (+ pad sentinels), counts
// No intra-kernel dependency between the two roles.
// ---------------------------------------------------------------------------
__global__ void __launch_bounds__(256)
prep_kernel(const float* __restrict__ emb,
            const int*   __restrict__ labels)
{
    const int b   = blockIdx.y;
    const int tid = threadIdx.x;
    const int warp = tid >> 5, lane = tid & 31;

    if (blockIdx.x == 32) {
        // ---------------- scan CTA: build index lists ----------------
        __shared__ int s_wtot[8];

        int4 l4 = reinterpret_cast<const int4*>(labels + b * NN)[tid];
        int p0 = (l4.x == 1), p1 = (l4.y == 1), p2 = (l4.z == 1), p3 = (l4.w == 1);
        int tsum = p0 + p1 + p2 + p3;

        int incl = tsum;
#pragma unroll
        for (int o = 1; o < 32; o <<= 1) {
            int u = __shfl_up_sync(0xFFFFFFFFu, incl, o);
            if (lane >= o) incl += u;
        }
        if (lane == 31) s_wtot[warp] = incl;
        __syncthreads();
        if (tid < 8) {
            int w = s_wtot[tid];
#pragma unroll
            for (int o = 1; o < 8; o <<= 1) {
                int u = __shfl_up_sync(0x000000FFu, w, o);
                if (lane >= o) w += u;
            }
            s_wtot[tid] = w;
        }
        __syncthreads();

        int run = (warp > 0 ? s_wtot[warp - 1] : 0) + incl - tsum;
        const int base4 = tid * 4;
        int pp[4] = {p0, p1, p2, p3};
#pragma unroll
        for (int j = 0; j < 4; j++) {
            int idx = base4 + j;
            if (pp[j]) g_pidx[b * NN + run]         = idx;
            else       g_nidx[b * NN + (idx - run)] = idx;
            run += pp[j];
        }

        const int npos = s_wtot[7];
        const int nneg = NN - npos;
        if (tid == 0) {
            g_npos[b] = npos; g_nneg[b] = nneg; g_bsum[b] = 0.0f;
            if (b == 0) g_done = 0u;
        }

        // pad index lists to 128-multiples with sentinel NN (the zero row)
        int pad_pos = min(NN, ((npos + TM - 1) / TM) * TM);
        int pad_neg = min(NN, ((nneg + TN - 1) / TN) * TN);
        for (int i = npos + tid; i < pad_pos; i += 256) g_pidx[b * NN + i] = NN;
        for (int i = nneg + tid; i < pad_neg; i += 256) g_nidx[b * NN + i] = NN;
        return;
    }

    // ---------------- normalize CTA: natural-order rows ----------------
    const int r0 = blockIdx.x * 32 + warp * 4;    // 4 consecutive rows per warp

    float4 v[4];
#pragma unroll
    for (int j = 0; j < 4; j++)
        v[j] = reinterpret_cast<const float4*>(emb + ((size_t)b * NN + r0 + j) * ND)[lane];

    float ss[4];
#pragma unroll
    for (int j = 0; j < 4; j++)
        ss[j] = v[j].x * v[j].x + v[j].y * v[j].y + v[j].z * v[j].z + v[j].w * v[j].w;
#pragma unroll
    for (int o = 16; o > 0; o >>= 1) {
#pragma unroll
        for (int j = 0; j < 4; j++) ss[j] += __shfl_xor_sync(0xFFFFFFFFu, ss[j], o);
    }

#pragma unroll
    for (int j = 0; j < 4; j++) {
        float inv = 1.0f / fmaxf(sqrtf(ss[j]), 1e-12f);
        __nv_bfloat16* dst = g_E + ((size_t)b * NNP + r0 + j) * ND;
        __nv_bfloat162 h0 = __floats2bfloat162_rn(v[j].x * inv, v[j].y * inv);
        __nv_bfloat162 h1 = __floats2bfloat162_rn(v[j].z * inv, v[j].w * inv);
        uint2 pk = make_uint2(*reinterpret_cast<uint32_t*>(&h0),
                              *reinterpret_cast<uint32_t*>(&h1));
        reinterpret_cast<uint2*>(dst)[lane] = pk;
    }
}

// ---------------------------------------------------------------------------
// Kernel B: A-resident streaming GEMM with row gather via index lists.
// CTA = (ti, b); grid (8,64), 256 threads, occ 2. Epilogue: max(x,T)-sum trick.
// ---------------------------------------------------------------------------
__global__ void __launch_bounds__(256, 2)
hinge_gemm_kernel(float* __restrict__ out)
{
    extern __shared__ __align__(16) char smem[];
    const uint32_t smem_base = smem_u32(smem);
    const int tid  = threadIdx.x;
    const int warp = tid >> 5;
    const int lane = tid & 31;

    __shared__ int s_pidx[TM];
    __shared__ int s_nidx[NN];

    const int ti = blockIdx.x;
    const int b  = blockIdx.y;
    const int npos = g_npos[b];
    const int nneg = g_nneg[b];
    const int njt  = (nneg + TN - 1) / TN;
    const bool active = (ti * TM < npos) && (njt > 0);

    if (active) {
        const char* Eb = (const char*)(g_E + (size_t)b * NNP * ND);

        // stage index lists (L2-hot)
        if (tid < TM) s_pidx[tid] = g_pidx[b * NN + ti * TM + tid];
#pragma unroll
        for (int j = 0; j < 4; j++) s_nidx[tid + j * 256] = g_nidx[b * NN + tid + j * 256];
        __syncthreads();

        const uint32_t sAa  = smem_base;
        const uint32_t sB0a = smem_base + TILE_BYTES;

        // load A (gathered) + first B tile, one group
        for (int t = tid; t < TM * 16; t += 256) {
            int r = t >> 4, c = t & 15;
            cp16(sAa + r * ROWB + c * 16, Eb + (size_t)s_pidx[r] * (ND * 2) + c * 16);
            cp16(sB0a + r * ROWB + c * 16, Eb + (size_t)s_nidx[r] * (ND * 2) + c * 16);
        }
        CP_COMMIT();

        const __nv_bfloat16* sA = (const __nv_bfloat16*)(smem);
        const int wrow = warp >> 1;
        const int wcol = warp & 1;

        float s0 = 0.0f, s1 = 0.0f, s2 = 0.0f, s3 = 0.0f;

        for (int tj = 0; tj < njt; tj++) {
            const int cbuf = tj & 1;
            if (tj + 1 < njt) {
                const int* nid = &s_nidx[(tj + 1) * TN];
                uint32_t sBn = smem_base + TILE_BYTES * (1 + ((tj + 1) & 1));
                for (int t = tid; t < TN * 16; t += 256) {
                    int r = t >> 4, c = t & 15;
                    cp16(sBn + r * ROWB + c * 16, Eb + (size_t)nid[r] * (ND * 2) + c * 16);
                }
                CP_COMMIT();
                CP_WAIT(1);
            } else {
                CP_WAIT(0);
            }
            __syncthreads();

            const __nv_bfloat16* sB =
                (const __nv_bfloat16*)(smem + TILE_BYTES * (1 + cbuf));

            wmma::fragment<wmma::accumulator, 16, 16, 16, float> acc[2][4];
#pragma unroll
            for (int i = 0; i < 2; i++)
#pragma unroll
                for (int j = 0; j < 4; j++) wmma::fill_fragment(acc[i][j], 0.0f);

#pragma unroll
            for (int k = 0; k < ND; k += 16) {
                wmma::fragment<wmma::matrix_a, 16, 16, 16, __nv_bfloat16, wmma::row_major> a[2];
                wmma::fragment<wmma::matrix_b, 16, 16, 16, __nv_bfloat16, wmma::col_major> bb[4];
#pragma unroll
                for (int i = 0; i < 2; i++)
                    wmma::load_matrix_sync(a[i], sA + (wrow * 32 + i * 16) * LDSE + k, LDSE);
#pragma unroll
                for (int j = 0; j < 4; j++)
                    wmma::load_matrix_sync(bb[j], sB + (wcol * 64 + j * 16) * LDSE + k, LDSE);
#pragma unroll
                for (int i = 0; i < 2; i++)
#pragma unroll
                    for (int j = 0; j < 4; j++)
                        wmma::mma_sync(acc[i][j], a[i], bb[j], acc[i][j]);
            }

            // epilogue: relu(x-T) = max(x,T) - T; accumulate max only (2 ops/elem)
#pragma unroll
            for (int i = 0; i < 2; i++)
#pragma unroll
                for (int j = 0; j < 4; j++) {
#pragma unroll
                    for (int e = 0; e < 8; e += 4) {
                        s0 += fmaxf(acc[i][j].x[e + 0], THRESH);
                        s1 += fmaxf(acc[i][j].x[e + 1], THRESH);
                        s2 += fmaxf(acc[i][j].x[e + 2], THRESH);
                        s3 += fmaxf(acc[i][j].x[e + 3], THRESH);
                    }
                }

            __syncthreads();
        }

        // subtract T * (64 elements/tile * njt tiles) once
        float s = ((s0 + s1) + (s2 + s3)) - 64.0f * (float)njt * THRESH;
#pragma unroll
        for (int o = 16; o > 0; o >>= 1) s += __shfl_xor_sync(0xFFFFFFFFu, s, o);
        __shared__ float s_w[8];
        if (lane == 0) s_w[warp] = s;
        __syncthreads();
        if (tid == 0) {
            float ts = 0.0f;
#pragma unroll
            for (int i = 0; i < 8; i++) ts += s_w[i];
            atomicAdd(&g_bsum[b], ts);
        }
    }

    // completion ticket; last CTA computes the final scalar
    __shared__ unsigned int s_rank;
    if (tid == 0) {
        __threadfence();
        s_rank = atomicAdd(&g_done, 1u);
    }
    __syncthreads();
    if (s_rank == GEMM_CTAS - 1 && tid == 0) {
        __threadfence();
        float L = 0.0f, C = 0.0f;
        for (int i = 0; i < NB; i++) {
            int np = g_npos[i], nn = g_nneg[i];
            if (np > 0 && nn > 0) {
                L += g_bsum[i] / (float)nn;
                C += (float)np;
            }
        }
        out[0] = L / fmaxf(C, 1.0f);
    }
}

// ---------------------------------------------------------------------------
extern "C" void kernel_launch(void* const* d_in, const int* in_sizes, int n_in,
                              void* d_out, int out_size)
{
    const float* emb    = (const float*)d_in[0];
    const int*   labels = (const int*)d_in[1];
    float*       out    = (float*)d_out;

    cudaFuncSetAttribute(hinge_gemm_kernel,
                         cudaFuncAttributeMaxDynamicSharedMemorySize, SMEM_DYN);

    dim3 gridA(33, NB);    // x<32 normalize, x==32 scan
    prep_kernel<<<gridA, 256>>>(emb, labels);

    dim3 gridB(8, NB);     // (ti, b) = 512 CTAs
    hinge_gemm_kernel<<<gridB, 256, SMEM_DYN>>>(out);
}

// round 17
// speedup vs baseline: 1.2021x; 1.1156x over previous
#include <cuda_runtime.h>
#include <cuda_fp16.h>
#include <mma.h>
#include <cstdint>

using namespace nvcuda;

#define NB 64
#define NN 1024
#define NNP 1025          // +1 always-zero row per batch (gather pad target)
#define ND 128
#define THRESH 0.15f      // 0.5 - MARGIN(0.35)
#define TM 128
#define TN 128
#define LDSE 136          // smem leading dim in fp16 elems (272B rows)
#define ROWB (LDSE * 2)
#define TILE_BYTES (TM * ROWB)        // 34816
#define SMEM_DYN (3 * TILE_BYTES)     // A + 2x B = 104448 (occ 2)
#define GEMM_CTAS (8 * NB)            // 512

// Scratch (device globals; no allocation allowed).
// g_E row NN of each batch is NEVER written -> stays zero (BSS) across replays.
__device__ __half g_E[(size_t)NB * NNP * ND];
__device__ int   g_pidx[NB * NN];
__device__ int   g_nidx[NB * NN];
__device__ int   g_npos[NB];
__device__ int   g_nneg[NB];
__device__ float g_bsum[NB];
__device__ unsigned int g_done;

__device__ __forceinline__ uint32_t smem_u32(const void* p) {
    uint32_t a;
    asm("{ .reg .u64 t; cvta.to.shared.u64 t, %1; cvt.u32.u64 %0, t; }" : "=r"(a) : "l"(p));
    return a;
}
__device__ __forceinline__ void cp16(uint32_t dst, const void* src) {
    asm volatile("cp.async.cg.shared.global [%0], [%1], 16;" :: "r"(dst), "l"(src));
}
#define CP_COMMIT() asm volatile("cp.async.commit_group;" ::: "memory")
#define CP_WAIT(n)  asm volatile("cp.async.wait_group %0;" :: "n"(n) : "memory")

// ---------------------------------------------------------------------------
// Kernel A: grid (33, 64), 256 threads.
//   x < 32 : normalize rows x*32..x*32+31 in NATURAL order (no scan needed)
//   x == 32: scan CTA -> index lists g_pidx/g_nidx (+ pad sentinels), counts
// ---------------------------------------------------------------------------
__global__ void __launch_bounds__(256)
prep_kernel(const float* __restrict__ emb,
            const int*   __restrict__ labels)
{
    const int b   = blockIdx.y;
    const int tid = threadIdx.x;
    const int warp = tid >> 5, lane = tid & 31;

    if (blockIdx.x == 32) {
        // ---------------- scan CTA: build index lists ----------------
        __shared__ int s_wtot[8];

        int4 l4 = reinterpret_cast<const int4*>(labels + b * NN)[tid];
        int p0 = (l4.x == 1), p1 = (l4.y == 1), p2 = (l4.z == 1), p3 = (l4.w == 1);
        int tsum = p0 + p1 + p2 + p3;

        int incl = tsum;
#pragma unroll
        for (int o = 1; o < 32; o <<= 1) {
            int u = __shfl_up_sync(0xFFFFFFFFu, incl, o);
            if (lane >= o) incl += u;
        }
        if (lane == 31) s_wtot[warp] = incl;
        __syncthreads();
        if (tid < 8) {
            int w = s_wtot[tid];
#pragma unroll
            for (int o = 1; o < 8; o <<= 1) {
                int u = __shfl_up_sync(0x000000FFu, w, o);
                if (lane >= o) w += u;
            }
            s_wtot[tid] = w;
        }
        __syncthreads();

        int run = (warp > 0 ? s_wtot[warp - 1] : 0) + incl - tsum;
        const int base4 = tid * 4;
        int pp[4] = {p0, p1, p2, p3};
#pragma unroll
        for (int j = 0; j < 4; j++) {
            int idx = base4 + j;
            if (pp[j]) g_pidx[b * NN + run]         = idx;
            else       g_nidx[b * NN + (idx - run)] = idx;
            run += pp[j];
        }

        const int npos = s_wtot[7];
        const int nneg = NN - npos;
        if (tid == 0) {
            g_npos[b] = npos; g_nneg[b] = nneg; g_bsum[b] = 0.0f;
            if (b == 0) g_done = 0u;
        }

        // pad index lists to 128-multiples with sentinel NN (the zero row)
        int pad_pos = min(NN, ((npos + TM - 1) / TM) * TM);
        int pad_neg = min(NN, ((nneg + TN - 1) / TN) * TN);
        for (int i = npos + tid; i < pad_pos; i += 256) g_pidx[b * NN + i] = NN;
        for (int i = nneg + tid; i < pad_neg; i += 256) g_nidx[b * NN + i] = NN;
        return;
    }

    // ---------------- normalize CTA: natural-order rows ----------------
    const int r0 = blockIdx.x * 32 + warp * 4;    // 4 consecutive rows per warp

    float4 v[4];
#pragma unroll
    for (int j = 0; j < 4; j++)
        v[j] = reinterpret_cast<const float4*>(emb + ((size_t)b * NN + r0 + j) * ND)[lane];

    float ss[4];
#pragma unroll
    for (int j = 0; j < 4; j++)
        ss[j] = v[j].x * v[j].x + v[j].y * v[j].y + v[j].z * v[j].z + v[j].w * v[j].w;
#pragma unroll
    for (int o = 16; o > 0; o >>= 1) {
#pragma unroll
        for (int j = 0; j < 4; j++) ss[j] += __shfl_xor_sync(0xFFFFFFFFu, ss[j], o);
    }

#pragma unroll
    for (int j = 0; j < 4; j++) {
        float inv = 1.0f / fmaxf(sqrtf(ss[j]), 1e-12f);
        __half* dst = g_E + ((size_t)b * NNP + r0 + j) * ND;
        __half2 h0 = __floats2half2_rn(v[j].x * inv, v[j].y * inv);
        __half2 h1 = __floats2half2_rn(v[j].z * inv, v[j].w * inv);
        uint2 pk = make_uint2(*reinterpret_cast<uint32_t*>(&h0),
                              *reinterpret_cast<uint32_t*>(&h1));
        reinterpret_cast<uint2*>(dst)[lane] = pk;
    }
}

// ---------------------------------------------------------------------------
// Kernel B: A-resident streaming GEMM, fp16 accumulate (2x HMMA rate),
// row gather via index lists. CTA = (ti, b); grid (8,64), 256 thr, occ 2.
// ---------------------------------------------------------------------------
__global__ void __launch_bounds__(256, 2)
hinge_gemm_kernel(float* __restrict__ out)
{
    extern __shared__ __align__(16) char smem[];
    const uint32_t smem_base = smem_u32(smem);
    const int tid  = threadIdx.x;
    const int warp = tid >> 5;
    const int lane = tid & 31;

    __shared__ int s_pidx[TM];
    __shared__ int s_nidx[NN];

    const int ti = blockIdx.x;
    const int b  = blockIdx.y;
    const int npos = g_npos[b];
    const int nneg = g_nneg[b];
    const int njt  = (nneg + TN - 1) / TN;
    const bool active = (ti * TM < npos) && (njt > 0);

    if (active) {
        const char* Eb = (const char*)(g_E + (size_t)b * NNP * ND);

        // stage index lists (L2-hot)
        if (tid < TM) s_pidx[tid] = g_pidx[b * NN + ti * TM + tid];
#pragma unroll
        for (int j = 0; j < 4; j++) s_nidx[tid + j * 256] = g_nidx[b * NN + tid + j * 256];
        __syncthreads();

        const uint32_t sAa  = smem_base;
        const uint32_t sB0a = smem_base + TILE_BYTES;

        // load A (gathered) + first B tile, one group
        for (int t = tid; t < TM * 16; t += 256) {
            int r = t >> 4, c = t & 15;
            cp16(sAa + r * ROWB + c * 16, Eb + (size_t)s_pidx[r] * (ND * 2) + c * 16);
            cp16(sB0a + r * ROWB + c * 16, Eb + (size_t)s_nidx[r] * (ND * 2) + c * 16);
        }
        CP_COMMIT();

        const __half* sA = (const __half*)(smem);
        const int wrow = warp >> 1;
        const int wcol = warp & 1;

        float s0 = 0.0f, s1 = 0.0f, s2 = 0.0f, s3 = 0.0f;

        for (int tj = 0; tj < njt; tj++) {
            const int cbuf = tj & 1;
            if (tj + 1 < njt) {
                const int* nid = &s_nidx[(tj + 1) * TN];
                uint32_t sBn = smem_base + TILE_BYTES * (1 + ((tj + 1) & 1));
                for (int t = tid; t < TN * 16; t += 256) {
                    int r = t >> 4, c = t & 15;
                    cp16(sBn + r * ROWB + c * 16, Eb + (size_t)nid[r] * (ND * 2) + c * 16);
                }
                CP_COMMIT();
                CP_WAIT(1);
            } else {
                CP_WAIT(0);
            }
            __syncthreads();

            const __half* sB = (const __half*)(smem + TILE_BYTES * (1 + cbuf));

            wmma::fragment<wmma::accumulator, 16, 16, 16, __half> acc[2][4];
#pragma unroll
            for (int i = 0; i < 2; i++)
#pragma unroll
                for (int j = 0; j < 4; j++)
                    wmma::fill_fragment(acc[i][j], __float2half(0.0f));

#pragma unroll
            for (int k = 0; k < ND; k += 16) {
                wmma::fragment<wmma::matrix_a, 16, 16, 16, __half, wmma::row_major> a[2];
                wmma::fragment<wmma::matrix_b, 16, 16, 16, __half, wmma::col_major> bb[4];
#pragma unroll
                for (int i = 0; i < 2; i++)
                    wmma::load_matrix_sync(a[i], sA + (wrow * 32 + i * 16) * LDSE + k, LDSE);
#pragma unroll
                for (int j = 0; j < 4; j++)
                    wmma::load_matrix_sync(bb[j], sB + (wcol * 64 + j * 16) * LDSE + k, LDSE);
#pragma unroll
                for (int i = 0; i < 2; i++)
#pragma unroll
                    for (int j = 0; j < 4; j++)
                        wmma::mma_sync(acc[i][j], a[i], bb[j], acc[i][j]);
            }

            // epilogue: relu(x-T) = max(x,T) - T; convert h->f, 4 partials
#pragma unroll
            for (int i = 0; i < 2; i++)
#pragma unroll
                for (int j = 0; j < 4; j++) {
#pragma unroll
                    for (int e = 0; e < 8; e += 4) {
                        s0 += fmaxf(__half2float(acc[i][j].x[e + 0]), THRESH);
                        s1 += fmaxf(__half2float(acc[i][j].x[e + 1]), THRESH);
                        s2 += fmaxf(__half2float(acc[i][j].x[e + 2]), THRESH);
                        s3 += fmaxf(__half2float(acc[i][j].x[e + 3]), THRESH);
                    }
                }

            __syncthreads();
        }

        // subtract T * (64 elements/tile * njt tiles) once
        float s = ((s0 + s1) + (s2 + s3)) - 64.0f * (float)njt * THRESH;
#pragma unroll
        for (int o = 16; o > 0; o >>= 1) s += __shfl_xor_sync(0xFFFFFFFFu, s, o);
        __shared__ float s_w[8];
        if (lane == 0) s_w[warp] = s;
        __syncthreads();
        if (tid == 0) {
            float ts = 0.0f;
#pragma unroll
            for (int i = 0; i < 8; i++) ts += s_w[i];
            atomicAdd(&g_bsum[b], ts);
        }
    }

    // completion ticket; last CTA computes the final scalar
    __shared__ unsigned int s_rank;
    if (tid == 0) {
        __threadfence();
        s_rank = atomicAdd(&g_done, 1u);
    }
    __syncthreads();
    if (s_rank == GEMM_CTAS - 1 && tid == 0) {
        __threadfence();
        float L = 0.0f, C = 0.0f;
        for (int i = 0; i < NB; i++) {
            int np = g_npos[i], nn = g_nneg[i];
            if (np > 0 && nn > 0) {
                L += g_bsum[i] / (float)nn;
                C += (float)np;
            }
        }
        out[0] = L / fmaxf(C, 1.0f);
    }
}

// ---------------------------------------------------------------------------
extern "C" void kernel_launch(void* const* d_in, const int* in_sizes, int n_in,
                              void* d_out, int out_size)
{
    const float* emb    = (const float*)d_in[0];
    const int*   labels = (const int*)d_in[1];
    float*       out    = (float*)d_out;

    cudaFuncSetAttribute(hinge_gemm_kernel,
                         cudaFuncAttributeMaxDynamicSharedMemorySize, SMEM_DYN);

    dim3 gridA(33, NB);    // x<32 normalize, x==32 scan
    prep_kernel<<<gridA, 256>>>(emb, labels);

    dim3 gridB(8, NB);     // (ti, b) = 512 CTAs
    hinge_gemm_kernel<<<gridB, 256, SMEM_DYN>>>(out);
}